// round 8
// baseline (speedup 1.0000x reference)
#include <cuda_runtime.h>
#include <cuda_bf16.h>
#include <math.h>

// Problem constants
#define B_  4096
#define T_  200
#define E_  64
#define A1_ 64
#define A2_ 32
#define M1_ 256
#define M2_ 128
#define GRID_MAIN 296   // 2 CTAs per SM x 148 SMs

// -------- device scratch (no allocations allowed) --------
__device__ float g_inter[B_ * 64]; // interest vectors

// ---- tf32 helpers ----
__device__ __forceinline__ unsigned int f2tf(float f) {
    unsigned int r;
    asm("cvt.rna.tf32.f32 %0, %1;" : "=r"(r) : "f"(f));
    return r;
}
__device__ __forceinline__ void split_tf32(float x, unsigned int& hi, unsigned int& lo) {
    hi = f2tf(x);
    lo = f2tf(x - __uint_as_float(hi));
}
__device__ __forceinline__ void mma_tf32(
    float& c0, float& c1, float& c2, float& c3,
    unsigned int a0, unsigned int a1, unsigned int a2, unsigned int a3,
    unsigned int b0, unsigned int b1) {
    asm("mma.sync.aligned.m16n8k8.row.col.f32.tf32.tf32.f32 "
        "{%0,%1,%2,%3},{%4,%5,%6,%7},{%8,%9},{%0,%1,%2,%3};"
        : "+f"(c0), "+f"(c1), "+f"(c2), "+f"(c3)
        : "r"(a0), "r"(a1), "r"(a2), "r"(a3), "r"(b0), "r"(b1));
}

// ============================================================
// main kernel: PERSISTENT, 296 CTAs x 512 threads, 2 CTAs/SM.
// Prologue folds aw1 -> Whp(bf16x2), Wq(bf16) in smem (no prep kernel).
// ============================================================
#define PH 68
// smem layout (float offsets)
#define OFF_HIST  0        // 208*68 = 14144
#define OFF_WCU   14144    // 4352
#define OFF_W2U   18496    // 2304
#define OFF_QV    20800    // 64
#define OFF_QB    20864    // 64
#define OFF_AB2   20928    // 32
#define OFF_AOW   20960    // 32
#define OFF_SC    20992    // 208
#define OFF_MSK   21200    // 208 (int view)
#define OFF_WRED  21408    // 32
#define OFF_RED   21440    // 512
#define OFF_WHPB  21952    // 4096 (bf16x2 packed Wh,Wp)
#define OFF_WQB   26048    // 2048 (bf16 Wq, 4096 halves)
#define SMEM_B_FLOATS 28096
#define SMEM_B_BYTES  (SMEM_B_FLOATS * 4)

__global__ __launch_bounds__(512, 2) void din_main(
    const int* __restrict__ hist_id,
    const int* __restrict__ mask,        // bool promoted to 4-byte; test != 0
    const float* __restrict__ table,
    const int* __restrict__ target,
    const float* __restrict__ aw1,
    const float* __restrict__ ab1,
    const float* __restrict__ aw2,
    const float* __restrict__ ab2,
    const float* __restrict__ aow,
    const float* __restrict__ aob) {
    extern __shared__ float sm[];
    unsigned int* smu = (unsigned int*)sm;
    int* smi = (int*)sm;
    __nv_bfloat162* whpb = (__nv_bfloat162*)(smu + OFF_WHPB);
    __nv_bfloat16*  wqb  = (__nv_bfloat16*)(smu + OFF_WQB);
    const int tid = threadIdx.x;
    const int w   = tid >> 5;
    const int l   = tid & 31;
    const int l4  = l >> 2;   // 0..7
    const int lm  = l & 3;    // 0..3

    // ---- loop-invariant staging (once per CTA) ----
    if (tid < 32)        sm[OFF_AB2 + tid]      = ab2[tid];
    else if (tid < 64)   sm[OFF_AOW + tid - 32] = aow[tid - 32];
    for (int idx = tid; idx < 64 * 32; idx += 512) {
        int n = idx & 31, k = idx >> 5;
        smu[OFF_W2U + k * 36 + n] = f2tf(aw2[k * 32 + n]);
    }
    // fold aw1 -> Whp (bf16 pair) + Wq (bf16), straight from gmem
    for (int idx = tid; idx < 64 * 64; idx += 512) {
        int j = idx & 63, k = idx >> 6;
        float a = aw1[k * 64 + j];
        float bb = aw1[(64 + k) * 64 + j];
        float c = aw1[(128 + k) * 64 + j];
        float d = aw1[(192 + k) * 64 + j];
        __nv_bfloat162 v;
        v.x = __float2bfloat16(a + c);   // Wh
        v.y = __float2bfloat16(d);       // Wp
        whpb[idx] = v;
        wqb[idx] = __float2bfloat16(bb - c);
    }
    const float aob0 = aob[0];
    const float ab1v = (tid < 64) ? ab1[tid] : 0.f;

    for (int b = blockIdx.x; b < B_; b += GRID_MAIN) {
        __syncthreads();   // B0: prior iteration done / invariants ready

        // --- per-batch staging: item embedding + mask ---
        if (tid < 64)
            sm[OFF_QV + tid] = table[(size_t)target[b] * 64 + tid];
        else if (tid < 264)
            smi[OFF_MSK + tid - 64] = mask[b * T_ + tid - 64];
        __syncthreads();   // B1: QV ready

        // --- qb partials: all 512 threads, LDS-only Wq ---
        {
            int n = tid & 63, kc = tid >> 6;
            float acc = 0.f;
#pragma unroll
            for (int i = 0; i < 8; ++i) {
                int k = kc * 8 + i;
                acc = fmaf(sm[OFF_QV + k], __bfloat162float(wqb[k * 64 + n]), acc);
            }
            sm[OFF_RED + kc * 64 + n] = acc;
        }
        __syncthreads();   // B1.5: partials ready
        if (tid < 64) {
            float acc = ab1v;
#pragma unroll
            for (int kc = 0; kc < 8; ++kc) acc += sm[OFF_RED + kc * 64 + tid];
            sm[OFF_QB + tid] = acc;
        }
        // --- fold Wc[k][n] = Wh + q[k]*Wp (LDS bf16 pairs), store tf32 bits ---
        for (int idx = tid; idx < 64 * 64; idx += 512) {
            int n = idx & 63, k = idx >> 6;
            __nv_bfloat162 hp = whpb[idx];
            smu[OFF_WCU + k * PH + n] =
                f2tf(fmaf(sm[OFF_QV + k], __bfloat162float(hp.y),
                          __bfloat162float(hp.x)));
        }
        // --- gather history embeddings ---
        {
            const float4* tab4 = (const float4*)table;
            float4* hist4 = (float4*)(sm + OFF_HIST);
            for (int idx = tid; idx < T_ * 16; idx += 512) {
                int t = idx >> 4, v = idx & 15;
                hist4[t * 17 + v] = tab4[(size_t)hist_id[b * T_ + t] * 16 + v];
            }
            for (int idx = tid; idx < 8 * 17; idx += 512) {
                int t = 200 + idx / 17, v = idx % 17;
                hist4[t * 17 + v] = make_float4(0.f, 0.f, 0.f, 0.f);
            }
        }
        __syncthreads();   // B2: all operands staged

        // ====== fused attention MLP: warps 0..12 own rows [16w, 16w+16) ======
        if (w < 13) {
            const int mt = w;

            unsigned int au[32];
            {
                const float* abase = sm + OFF_HIST + (mt * 16 + l4) * PH + lm;
#pragma unroll
                for (int k = 0; k < 8; ++k) {
                    au[4 * k + 0] = f2tf(abase[k * 8]);
                    au[4 * k + 1] = f2tf(abase[8 * PH + k * 8]);
                    au[4 * k + 2] = f2tf(abase[k * 8 + 4]);
                    au[4 * k + 3] = f2tf(abase[8 * PH + k * 8 + 4]);
                }
            }

            float d0[4], d1[4], d2[4], d3[4];
#pragma unroll
            for (int nt2 = 0; nt2 < 4; ++nt2) {
                float bb0 = sm[OFF_AB2 + nt2 * 8 + 2 * lm];
                float bb1 = sm[OFF_AB2 + nt2 * 8 + 2 * lm + 1];
                d0[nt2] = bb0; d1[nt2] = bb1; d2[nt2] = bb0; d3[nt2] = bb1;
            }

            const unsigned int* wc_col = smu + OFF_WCU + lm * PH;
            const unsigned int* w2_col = smu + OFF_W2U + lm * 36 + l4;

            for (int kk = 0; kk < 8; ++kk) {
                float c0 = sm[OFF_QB + kk * 8 + 2 * lm];
                float c1 = sm[OFF_QB + kk * 8 + 2 * lm + 1];
                float c2 = c0, c3 = c1;
                const unsigned int* wcb = wc_col + kk * 8 + l4;
#pragma unroll
                for (int k = 0; k < 8; ++k) {
                    unsigned int b0v = wcb[k * 8 * PH];
                    unsigned int b1v = wcb[k * 8 * PH + 4 * PH];
                    mma_tf32(c0, c1, c2, c3,
                             au[4 * k], au[4 * k + 1], au[4 * k + 2], au[4 * k + 3],
                             b0v, b1v);
                }
                c0 = fmaxf(c0, 0.f); c1 = fmaxf(c1, 0.f);
                c2 = fmaxf(c2, 0.f); c3 = fmaxf(c3, 0.f);

                int src1 = (l & ~3) + (lm >> 1);
                int src2 = src1 + 2;
                float v0a = __shfl_sync(0xffffffffu, c0, src1);
                float v1a = __shfl_sync(0xffffffffu, c1, src1);
                float v2a = __shfl_sync(0xffffffffu, c2, src1);
                float v3a = __shfl_sync(0xffffffffu, c3, src1);
                float v0b = __shfl_sync(0xffffffffu, c0, src2);
                float v1b = __shfl_sync(0xffffffffu, c1, src2);
                float v2b = __shfl_sync(0xffffffffu, c2, src2);
                float v3b = __shfl_sync(0xffffffffu, c3, src2);
                bool hi = (lm & 1);
                unsigned int a0 = f2tf(hi ? v1a : v0a);
                unsigned int a1 = f2tf(hi ? v3a : v2a);
                unsigned int a2 = f2tf(hi ? v1b : v0b);
                unsigned int a3 = f2tf(hi ? v3b : v2b);

                const unsigned int* w2b = w2_col + kk * 8 * 36;
#pragma unroll
                for (int nt2 = 0; nt2 < 4; ++nt2) {
                    unsigned int b0v = w2b[nt2 * 8];
                    unsigned int b1v = w2b[nt2 * 8 + 4 * 36];
                    mma_tf32(d0[nt2], d1[nt2], d2[nt2], d3[nt2],
                             a0, a1, a2, a3, b0v, b1v);
                }
            }

            float p01 = 0.f, p23 = 0.f;
#pragma unroll
            for (int nt2 = 0; nt2 < 4; ++nt2) {
                float w0 = sm[OFF_AOW + nt2 * 8 + 2 * lm];
                float w1 = sm[OFF_AOW + nt2 * 8 + 2 * lm + 1];
                p01 = fmaf(fmaxf(d0[nt2], 0.f), w0, fmaf(fmaxf(d1[nt2], 0.f), w1, p01));
                p23 = fmaf(fmaxf(d2[nt2], 0.f), w0, fmaf(fmaxf(d3[nt2], 0.f), w1, p23));
            }
            p01 += __shfl_xor_sync(0xffffffffu, p01, 1);
            p01 += __shfl_xor_sync(0xffffffffu, p01, 2);
            p23 += __shfl_xor_sync(0xffffffffu, p23, 1);
            p23 += __shfl_xor_sync(0xffffffffu, p23, 2);
            if (lm == 0) {
                int r0 = mt * 16 + l4;
                int r1 = r0 + 8;
                if (r0 < T_)
                    sm[OFF_SC + r0] = (smi[OFF_MSK + r0] != 0) ? p01 + aob0 : -1e9f;
                if (r1 < T_)
                    sm[OFF_SC + r1] = (smi[OFF_MSK + r1] != 0) ? p23 + aob0 : -1e9f;
            }
        }
        __syncthreads();   // B3: scores ready

        // ---- softmax ----
        float v = (tid < T_) ? sm[OFF_SC + tid] : -1e30f;
        float m = v;
        m = fmaxf(m, __shfl_xor_sync(0xffffffffu, m, 16));
        m = fmaxf(m, __shfl_xor_sync(0xffffffffu, m, 8));
        m = fmaxf(m, __shfl_xor_sync(0xffffffffu, m, 4));
        m = fmaxf(m, __shfl_xor_sync(0xffffffffu, m, 2));
        m = fmaxf(m, __shfl_xor_sync(0xffffffffu, m, 1));
        if (l == 0) sm[OFF_WRED + w] = m;
        __syncthreads();   // B4
        float gm = sm[OFF_WRED + 0];
#pragma unroll
        for (int i = 1; i < 16; ++i) gm = fmaxf(gm, sm[OFF_WRED + i]);
        float e = (tid < T_) ? __expf(v - gm) : 0.f;
        if (tid < T_) sm[OFF_SC + tid] = e;
        float s = e;
        s += __shfl_xor_sync(0xffffffffu, s, 16);
        s += __shfl_xor_sync(0xffffffffu, s, 8);
        s += __shfl_xor_sync(0xffffffffu, s, 4);
        s += __shfl_xor_sync(0xffffffffu, s, 2);
        s += __shfl_xor_sync(0xffffffffu, s, 1);
        if (l == 0) sm[OFF_WRED + 16 + w] = s;
        __syncthreads();   // B5

        // ---- interest (normalization folded in) ----
        {
            float ss = sm[OFF_WRED + 16];
#pragma unroll
            for (int i = 1; i < 16; ++i) ss += sm[OFF_WRED + 16 + i];
            float inv = 1.f / ss;
            int j = tid & 63, g = tid >> 6;
            float acc = 0.f;
            for (int t = g * 25; t < (g + 1) * 25; ++t)
                acc = fmaf(sm[OFF_SC + t], sm[OFF_HIST + t * PH + j], acc);
            sm[OFF_RED + g * 64 + j] = acc * inv;
        }
        __syncthreads();   // B6
        if (tid < 64) {
            float iv = 0.f;
#pragma unroll
            for (int g = 0; g < 8; ++g) iv += sm[OFF_RED + g * 64 + tid];
            g_inter[b * 64 + tid] = iv;
        }
    }
}

// ============================================================
// final MLP v4: tf32x2 precision-split tensor cores (fp32-accurate).
// 256 threads, 32 rows/CTA, grid 128. Data staged fp32, split at frag load.
// ============================================================
#define DR  32
#define FPX 136
#define FPW 264
#define FX    0        // 32*136 = 4352 (fp32)
#define FG1   4352     // 32*264 = 8448 -> 12800 (fp32)
#define FWT   12800    // 32*264 = 8448 -> 21248 (fp32)
#define FMB1  21248    // 256
#define FMB2  21504    // 128
#define FOW   21632    // 128
#define FRED  21760    // 256
#define FTGT  22016    // 32 (int view)
#define SMEM_F_FLOATS 22048
#define SMEM_F_BYTES  (SMEM_F_FLOATS * 4)

__global__ __launch_bounds__(256) void din_final(
    const int* __restrict__ target,
    const float* __restrict__ table,
    const float* __restrict__ mw1, const float* __restrict__ mb1,
    const float* __restrict__ mw2, const float* __restrict__ mb2,
    const float* __restrict__ ow,  const float* __restrict__ ob,
    float* __restrict__ out) {
    extern __shared__ float sm[];
    int* smi = (int*)sm;
    const int tid = threadIdx.x;
    const int w   = tid >> 5;   // 0..7
    const int l   = tid & 31;
    const int l4  = l >> 2;
    const int lm  = l & 3;
    const int b0  = blockIdx.x * DR;

    if (tid < DR) smi[FTGT + tid] = target[b0 + tid];
    sm[FMB1 + tid] = mb1[tid];
    if (tid < 128) { sm[FMB2 + tid] = mb2[tid]; sm[FOW + tid] = ow[tid]; }
    __syncthreads();

    // ---- X = concat(item, interest), fp32 ----
    {
        const float4* tab4 = (const float4*)table;
        const float4* int4p = (const float4*)g_inter;
        for (int idx = tid; idx < DR * 32; idx += 256) {
            int rr = idx >> 5, v = idx & 31;
            float4 x = (v < 16)
                ? tab4[(size_t)smi[FTGT + rr] * 16 + v]
                : int4p[(size_t)(b0 + rr) * 16 + (v - 16)];
            *(float4*)(sm + FX + rr * FPX + v * 4) = x;
        }
    }

    // ---- stage 1: acc1 = X @ mw1 + mb1 (warp w owns cols [32w,32w+32)) ----
    const int n0w = w * 32;
    float acc1[32];
#pragma unroll
    for (int nt = 0; nt < 4; ++nt) {
        float bb0 = sm[FMB1 + n0w + nt * 8 + 2 * lm];
        float bb1 = sm[FMB1 + n0w + nt * 8 + 2 * lm + 1];
#pragma unroll
        for (int mt = 0; mt < 2; ++mt) {
            acc1[(mt * 4 + nt) * 4 + 0] = bb0;
            acc1[(mt * 4 + nt) * 4 + 1] = bb1;
            acc1[(mt * 4 + nt) * 4 + 2] = bb0;
            acc1[(mt * 4 + nt) * 4 + 3] = bb1;
        }
    }
    for (int c4 = 0; c4 < 4; ++c4) {
        __syncthreads();   // X ready (c4=0) / prior WT reads done
        {
            const float4* w4 = (const float4*)(mw1 + c4 * 32 * 256);
            for (int idx = tid; idx < 2048; idx += 256) {
                int r = idx >> 6, v = idx & 63;
                *(float4*)(sm + FWT + r * FPW + v * 4) = w4[r * 64 + v];
            }
        }
        __syncthreads();
#pragma unroll
        for (int s = 0; s < 4; ++s) {
            unsigned int ah[2][4], al[2][4];
#pragma unroll
            for (int mt = 0; mt < 2; ++mt) {
                const float* ab = sm + FX + (mt * 16 + l4) * FPX + c4 * 32 + s * 8 + lm;
                split_tf32(ab[0],           ah[mt][0], al[mt][0]);
                split_tf32(ab[8 * FPX],     ah[mt][1], al[mt][1]);
                split_tf32(ab[4],           ah[mt][2], al[mt][2]);
                split_tf32(ab[8 * FPX + 4], ah[mt][3], al[mt][3]);
            }
#pragma unroll
            for (int nt = 0; nt < 4; ++nt) {
                float b0f = sm[FWT + (s * 8 + lm) * FPW + n0w + nt * 8 + l4];
                float b1f = sm[FWT + (s * 8 + lm + 4) * FPW + n0w + nt * 8 + l4];
                unsigned int b0h, b0l, b1h, b1l;
                split_tf32(b0f, b0h, b0l);
                split_tf32(b1f, b1h, b1l);
#pragma unroll
                for (int mt = 0; mt < 2; ++mt) {
                    int base = (mt * 4 + nt) * 4;
                    mma_tf32(acc1[base + 0], acc1[base + 1], acc1[base + 2], acc1[base + 3],
                             ah[mt][0], ah[mt][1], ah[mt][2], ah[mt][3], b0h, b1h);
                    mma_tf32(acc1[base + 0], acc1[base + 1], acc1[base + 2], acc1[base + 3],
                             al[mt][0], al[mt][1], al[mt][2], al[mt][3], b0h, b1h);
                    mma_tf32(acc1[base + 0], acc1[base + 1], acc1[base + 2], acc1[base + 3],
                             ah[mt][0], ah[mt][1], ah[mt][2], ah[mt][3], b0l, b1l);
                }
            }
        }
    }
    // ---- G1 = relu(acc1), fp32 ----
#pragma unroll
    for (int mt = 0; mt < 2; ++mt)
#pragma unroll
        for (int nt = 0; nt < 4; ++nt) {
            int base = (mt * 4 + nt) * 4;
            int col = n0w + nt * 8 + 2 * lm;
            *(float2*)(sm + FG1 + (mt * 16 + l4) * FPW + col) =
                make_float2(fmaxf(acc1[base + 0], 0.f), fmaxf(acc1[base + 1], 0.f));
            *(float2*)(sm + FG1 + (mt * 16 + l4 + 8) * FPW + col) =
                make_float2(fmaxf(acc1[base + 2], 0.f), fmaxf(acc1[base + 3], 0.f));
        }

    // ---- stage 2: acc2 = G1 @ mw2 + mb2 (warp w owns cols [16w,16w+16)) ----
    const int n0w2 = w * 16;
    float acc2[16];
#pragma unroll
    for (int nt = 0; nt < 2; ++nt) {
        float bb0 = sm[FMB2 + n0w2 + nt * 8 + 2 * lm];
        float bb1 = sm[FMB2 + n0w2 + nt * 8 + 2 * lm + 1];
#pragma unroll
        for (int mt = 0; mt < 2; ++mt) {
            acc2[(mt * 2 + nt) * 4 + 0] = bb0;
            acc2[(mt * 2 + nt) * 4 + 1] = bb1;
            acc2[(mt * 2 + nt) * 4 + 2] = bb0;
            acc2[(mt * 2 + nt) * 4 + 3] = bb1;
        }
    }
    for (int c8 = 0; c8 < 8; ++c8) {
        __syncthreads();   // G1 writes done (c8=0) / prior WT reads done
        {
            const float4* w4 = (const float4*)(mw2 + c8 * 32 * 128);
            for (int idx = tid; idx < 1024; idx += 256) {
                int r = idx >> 5, v = idx & 31;
                *(float4*)(sm + FWT + r * FPX + v * 4) = w4[r * 32 + v];
            }
        }
        __syncthreads();
#pragma unroll
        for (int s = 0; s < 4; ++s) {
            unsigned int ah[2][4], al[2][4];
#pragma unroll
            for (int mt = 0; mt < 2; ++mt) {
                const float* ab = sm + FG1 + (mt * 16 + l4) * FPW + c8 * 32 + s * 8 + lm;
                split_tf32(ab[0],           ah[mt][0], al[mt][0]);
                split_tf32(ab[8 * FPW],     ah[mt][1], al[mt][1]);
                split_tf32(ab[4],           ah[mt][2], al[mt][2]);
                split_tf32(ab[8 * FPW + 4], ah[mt][3], al[mt][3]);
            }
#pragma unroll
            for (int nt = 0; nt < 2; ++nt) {
                float b0f = sm[FWT + (s * 8 + lm) * FPX + n0w2 + nt * 8 + l4];
                float b1f = sm[FWT + (s * 8 + lm + 4) * FPX + n0w2 + nt * 8 + l4];
                unsigned int b0h, b0l, b1h, b1l;
                split_tf32(b0f, b0h, b0l);
                split_tf32(b1f, b1h, b1l);
#pragma unroll
                for (int mt = 0; mt < 2; ++mt) {
                    int base = (mt * 2 + nt) * 4;
                    mma_tf32(acc2[base + 0], acc2[base + 1], acc2[base + 2], acc2[base + 3],
                             ah[mt][0], ah[mt][1], ah[mt][2], ah[mt][3], b0h, b1h);
                    mma_tf32(acc2[base + 0], acc2[base + 1], acc2[base + 2], acc2[base + 3],
                             al[mt][0], al[mt][1], al[mt][2], al[mt][3], b0h, b1h);
                    mma_tf32(acc2[base + 0], acc2[base + 1], acc2[base + 2], acc2[base + 3],
                             ah[mt][0], ah[mt][1], ah[mt][2], ah[mt][3], b0l, b1l);
                }
            }
        }
    }

    // ---- stage 3: out = relu(acc2) @ ow + ob ----
    float pA[2] = {0.f, 0.f}, pB[2] = {0.f, 0.f};
#pragma unroll
    for (int mt = 0; mt < 2; ++mt)
#pragma unroll
        for (int nt = 0; nt < 2; ++nt) {
            int base = (mt * 2 + nt) * 4;
            float w0 = sm[FOW + n0w2 + nt * 8 + 2 * lm];
            float w1 = sm[FOW + n0w2 + nt * 8 + 2 * lm + 1];
            pA[mt] = fmaf(fmaxf(acc2[base + 0], 0.f), w0,
                     fmaf(fmaxf(acc2[base + 1], 0.f), w1, pA[mt]));
            pB[mt] = fmaf(fmaxf(acc2[base + 2], 0.f), w0,
                     fmaf(fmaxf(acc2[base + 3], 0.f), w1, pB[mt]));
        }
#pragma unroll
    for (int mt = 0; mt < 2; ++mt) {
        pA[mt] += __shfl_xor_sync(0xffffffffu, pA[mt], 1);
        pA[mt] += __shfl_xor_sync(0xffffffffu, pA[mt], 2);
        pB[mt] += __shfl_xor_sync(0xffffffffu, pB[mt], 1);
        pB[mt] += __shfl_xor_sync(0xffffffffu, pB[mt], 2);
    }
    if (lm == 0) {
#pragma unroll
        for (int mt = 0; mt < 2; ++mt) {
            sm[FRED + w * 32 + mt * 16 + l4]     = pA[mt];
            sm[FRED + w * 32 + mt * 16 + l4 + 8] = pB[mt];
        }
    }
    __syncthreads();
    if (tid < DR) {
        float p = ob[0];
#pragma unroll
        for (int w8 = 0; w8 < 8; ++w8) p += sm[FRED + w8 * 32 + tid];
        out[b0 + tid] = p;
    }
}

// ============================================================
// launch
// ============================================================
extern "C" void kernel_launch(void* const* d_in, const int* in_sizes, int n_in,
                              void* d_out, int out_size) {
    const int*   target  = (const int*)d_in[0];
    const int*   hist_id = (const int*)d_in[1];
    const int*   mask    = (const int*)d_in[2];     // bool promoted; test != 0
    const float* table   = (const float*)d_in[3];
    const float* aw1     = (const float*)d_in[4];
    const float* ab1     = (const float*)d_in[5];
    const float* aw2     = (const float*)d_in[6];
    const float* ab2     = (const float*)d_in[7];
    const float* aow     = (const float*)d_in[8];
    const float* aob     = (const float*)d_in[9];
    const float* mw1     = (const float*)d_in[10];
    const float* mb1     = (const float*)d_in[11];
    const float* mw2     = (const float*)d_in[12];
    const float* mb2     = (const float*)d_in[13];
    const float* ow      = (const float*)d_in[14];
    const float* ob      = (const float*)d_in[15];
    float* out = (float*)d_out;

    cudaFuncSetAttribute(din_main, cudaFuncAttributeMaxDynamicSharedMemorySize, SMEM_B_BYTES);
    cudaFuncSetAttribute(din_final, cudaFuncAttributeMaxDynamicSharedMemorySize, SMEM_F_BYTES);

    din_main<<<GRID_MAIN, 512, SMEM_B_BYTES>>>(hist_id, mask, table, target, aw1,
                                               ab1, aw2, ab2, aow, aob);
    din_final<<<B_ / DR, 256, SMEM_F_BYTES>>>(target, table, mw1, mb1,
                                              mw2, mb2, ow, ob, out);
}